// round 6
// baseline (speedup 1.0000x reference)
#include <cuda_runtime.h>

#define HN 50
#define TN 512
#define BN 2048
#define NT 224   // 7 warps

typedef unsigned long long u64;

__device__ __forceinline__ u64 pack2(float x, float y) {
    u64 r; asm("mov.b64 %0, {%1, %2};" : "=l"(r) : "f"(x), "f"(y)); return r;
}
__device__ __forceinline__ void unpack2(u64 v, float &x, float &y) {
    asm("mov.b64 {%0, %1}, %2;" : "=f"(x), "=f"(y) : "l"(v));
}
__device__ __forceinline__ u64 fma2(u64 a, u64 b, u64 c) {
    u64 r; asm("fma.rn.f32x2 %0, %1, %2, %3;" : "=l"(r) : "l"(a), "l"(b), "l"(c)); return r;
}
__device__ __forceinline__ u64 add2(u64 a, u64 b) {
    u64 r; asm("add.rn.f32x2 %0, %1, %2;" : "=l"(r) : "l"(a), "l"(b)); return r;
}

// Proven numerics (rel_err ~4e-7 in R4/R5): EX2 + RCP based sigmoid.
__device__ __forceinline__ float sigmoid_f(float x) {
    float e = __expf(-x);
    return __fdividef(1.0f, 1.0f + e);
}

__global__ void __launch_bounds__(NT, 4)
lstm_kernel(const float* __restrict__ x,     // [B, T, 1]
            const float* __restrict__ W_ih,  // [4H, 1]
            const float* __restrict__ W_hh,  // [4H, H]
            const float* __restrict__ b_ih,  // [4H]
            const float* __restrict__ b_hh,  // [4H]
            const float* __restrict__ W_lin, // [1, H]
            const float* __restrict__ b_lin, // [1]
            float* __restrict__ out)         // [B, 1]
{
    // h rows: [0..49]=h, [50]=1 (bias lane), [51]=x_t, rest pad. 64-float stride.
    __shared__ __align__(16) float hbuf[2][64];
    __shared__ float xs[TN];

    const int b    = blockIdx.x;
    const int tid  = threadIdx.x;
    const int lane = tid & 31;
    const int w    = tid >> 5;
    const int j    = lane & 7;     // h-index within warp group
    const int g    = lane >> 3;    // 0=i, 1=f, 2=g, 3=o
    const int h    = 8 * w + j;    // 0..55, valid < 50
    const bool valid = (h < HN);
    const int  hc    = valid ? h : (HN - 1);
    const int  row   = g * HN + hc;        // PyTorch gate order i,f,g,o
    const bool is_f  = (g == 1);

    // Preload this sequence's x (coalesced).
    for (int t = tid; t < TN; t += NT) xs[t] = x[b * TN + t];

    // Init both h buffers: zeros, const-1 at [50], x_0 at buf0[51].
    if (tid < 128) {
        int idx = tid & 63;
        float v = 0.0f;
        if (idx == 50) v = 1.0f;
        if (idx == 51 && tid < 64) v = x[b * TN];   // buf0[51] = x_0
        ((float*)hbuf)[tid] = v;
    }

    // One gate row: 50 W_hh weights + (bias, w_ih) folded into slot 25.
    // g-gate rows prescaled by 2 so every lane runs plain sigmoid
    // (tanh(p) = 2*sigmoid(2p) - 1 recovered in the combine).
    u64 wr[26];
    {
        const float sc = (g == 2) ? 2.0f : 1.0f;
        const float2* wp = (const float2*)(W_hh + row * HN);  // 8B-aligned (200B stride)
        #pragma unroll
        for (int k = 0; k < 25; k++) {
            float2 f2 = wp[k];
            wr[k] = valid ? pack2(sc * f2.x, sc * f2.y) : 0ull;
        }
        wr[25] = valid ? pack2(sc * (b_ih[row] + b_hh[row]), sc * W_ih[row]) : 0ull;
    }

    float c = 0.0f;   // cell state, lives in valid f-lanes

    __syncthreads();

#define LSTM_STEP(HR, HW, T)                                                   \
    {                                                                          \
        const ulonglong2* h2 = (const ulonglong2*)&hbuf[HR][0];                \
        u64 a0 = 0ull, a1 = 0ull, a2 = 0ull, a3 = 0ull;                        \
        _Pragma("unroll")                                                      \
        for (int k = 0; k < 6; k++) {                                          \
            ulonglong2 v0 = h2[2 * k];                                         \
            ulonglong2 v1 = h2[2 * k + 1];                                     \
            a0 = fma2(wr[4 * k],     v0.x, a0);                                \
            a1 = fma2(wr[4 * k + 1], v0.y, a1);                                \
            a2 = fma2(wr[4 * k + 2], v1.x, a2);                                \
            a3 = fma2(wr[4 * k + 3], v1.y, a3);                                \
        }                                                                      \
        ulonglong2 vt = h2[12];              /* h[48],h[49] | 1, x_t */        \
        a0 = fma2(wr[24], vt.x, a0);                                           \
        a1 = fma2(wr[25], vt.y, a1);                                           \
        u64 ssum = add2(add2(a0, a2), add2(a1, a3));                           \
        float sx, sy; unpack2(ssum, sx, sy);                                   \
        float sA = sigmoid_f(sx + sy);       /* i | f | (tanh g+1)/2 | o */    \
        float v16 = __shfl_xor_sync(0xFFFFFFFFu, sA, 16); /* i<->g, f<->o */   \
        float tA  = sA + sA;                                                   \
        float ig  = fmaf(tA, v16, -sA);      /* i-lane: i*(2sg-1) = i*g */     \
        float val2 = (g == 0) ? ig : sA;                                       \
        float v8  = __shfl_xor_sync(0xFFFFFFFFu, val2, 8); /* ig -> f-lane */  \
        if (is_f && valid) {                                                   \
            c = fmaf(sA, c, v8);             /* c = f*c + i*g */               \
            float s2c = sigmoid_f(2.0f * c);                                   \
            float tv  = v16 + v16;           /* v16 = o on f-lane */           \
            hbuf[HW][h] = fmaf(tv, s2c, -v16); /* o * tanh(c) */               \
        }                                                                      \
        if (tid == 31 && (T) + 1 < TN) hbuf[HW][51] = xs[(T) + 1];             \
        __syncthreads();                                                       \
    }

    for (int t = 0; t < TN; t += 2) {
        LSTM_STEP(0, 1, t)
        LSTM_STEP(1, 0, t + 1)
    }
#undef LSTM_STEP

    // Final head: out[b] = h_final . W_lin + b_lin  (h_final in hbuf[0])
    if (tid == 0) {
        float s = b_lin[0];
        #pragma unroll
        for (int k = 0; k < HN; k++) s = fmaf(hbuf[0][k], W_lin[k], s);
        out[b] = s;
    }
}

extern "C" void kernel_launch(void* const* d_in, const int* in_sizes, int n_in,
                              void* d_out, int out_size) {
    const float* x     = (const float*)d_in[0];
    const float* W_ih  = (const float*)d_in[1];
    const float* W_hh  = (const float*)d_in[2];
    const float* b_ih  = (const float*)d_in[3];
    const float* b_hh  = (const float*)d_in[4];
    const float* W_lin = (const float*)d_in[5];
    const float* b_lin = (const float*)d_in[6];
    float* out = (float*)d_out;

    lstm_kernel<<<BN, NT>>>(x, W_ih, W_hh, b_ih, b_hh, W_lin, b_lin, out);
}

// round 7
// speedup vs baseline: 1.1700x; 1.1700x over previous
#include <cuda_runtime.h>

#define HN 50
#define TN 512
#define BN 2048

typedef unsigned long long u64;

__device__ __forceinline__ u64 pack2(float x, float y) {
    u64 r; asm("mov.b64 %0, {%1, %2};" : "=l"(r) : "f"(x), "f"(y)); return r;
}
__device__ __forceinline__ void unpack2(u64 v, float &x, float &y) {
    asm("mov.b64 {%0, %1}, %2;" : "=f"(x), "=f"(y) : "l"(v));
}
// Packed dual-fp32 FMA (Blackwell FFMA2): 2 MACs per issue.
__device__ __forceinline__ u64 fma2(u64 a, u64 b, u64 c) {
    u64 r; asm("fma.rn.f32x2 %0, %1, %2, %3;" : "=l"(r) : "l"(a), "l"(b), "l"(c)); return r;
}
__device__ __forceinline__ u64 add2(u64 a, u64 b) {
    u64 r; asm("add.rn.f32x2 %0, %1, %2;" : "=l"(r) : "l"(a), "l"(b)); return r;
}

// Proven numerics (rel_err ~4e-7 since R4): EX2 + RCP based sigmoid.
__device__ __forceinline__ float sigmoid_f(float x) {
    float e = __expf(-x);
    return __fdividef(1.0f, 1.0f + e);
}

// 26-slot f32x2 dual-row dot product over one h vector (52 floats incl. 1, x_t).
__device__ __forceinline__ void dot26(const u64* __restrict__ wA,
                                      const u64* __restrict__ wB,
                                      const float* __restrict__ hr,
                                      u64& as, u64& ds) {
    const ulonglong2* h2 = (const ulonglong2*)hr;
    u64 a0 = 0ull, a1 = 0ull, d0 = 0ull, d1 = 0ull;
    #pragma unroll
    for (int k = 0; k < 13; k++) {
        ulonglong2 v = h2[k];                 // LDS.128 broadcast
        a0 = fma2(wA[2 * k],     v.x, a0);
        a1 = fma2(wA[2 * k + 1], v.y, a1);
        d0 = fma2(wB[2 * k],     v.x, d0);
        d1 = fma2(wB[2 * k + 1], v.y, d1);
    }
    as = add2(a0, a1);
    ds = add2(d0, d1);
}

__global__ void __launch_bounds__(128, 3)
lstm_kernel(const float* __restrict__ x,     // [B, T, 1]
            const float* __restrict__ W_ih,  // [4H, 1]
            const float* __restrict__ W_hh,  // [4H, H]
            const float* __restrict__ b_ih,  // [4H]
            const float* __restrict__ b_hh,  // [4H]
            const float* __restrict__ W_lin, // [1, H]
            const float* __restrict__ b_lin, // [1]
            float* __restrict__ out)         // [B, 1]
{
    // Per batch, double-buffered h row: [0..49]=h, [50]=1, [51]=x_t, rest pad.
    __shared__ __align__(16) float hbuf[2][2][64];   // [batch][buf][64]
    __shared__ float xs[2][TN + 8];                  // padded: step T reads xs[T+1]

    const int b0   = blockIdx.x * 2;                 // two sequences per CTA
    const int tid  = threadIdx.x;
    const int lane = tid & 31;
    const int w    = tid >> 5;
    const int p    = (w << 4) | (lane & 15);         // pair h-index, 0..63
    const int role = lane >> 4;                      // 0 = IG lane, 1 = FO lane
    const bool valid = (p < HN);
    const int  pc    = valid ? p : (HN - 1);

    // Preload both x sequences (coalesced).
    for (int t = tid; t < TN; t += 128) {
        xs[0][t] = x[b0 * TN + t];
        xs[1][t] = x[(b0 + 1) * TN + t];
    }

    // Init h buffers: zeros, 1.0 at slot 50 (bias lane), x_0 at buf0 slot 51.
    for (int i = tid; i < 256; i += 128) {
        int idx = i & 63;
        ((float*)hbuf)[i] = (idx == 50) ? 1.0f : 0.0f;
    }
    if (tid == 0) {
        hbuf[0][0][51] = x[b0 * TN];
        hbuf[1][0][51] = x[(b0 + 1) * TN];
    }

    // Gate rows (PyTorch order i,f,g,o): rowA = i|f, rowB = g|o.
    // g rows (role 0, rowB) prescaled x2 so every lane runs plain sigmoid:
    // tanh(p) = 2*sigmoid(2p) - 1 recovered in the combine.
    const int rowA = pc + role * HN;
    const int rowB = rowA + 2 * HN;
    const float scB = role ? 1.0f : 2.0f;

    u64 wA[26], wB[26];
    {
        const float2* ra = (const float2*)(W_hh + rowA * HN);  // 200B row stride
        const float2* rb = (const float2*)(W_hh + rowB * HN);
        #pragma unroll
        for (int k = 0; k < 25; k++) {
            float2 fa = ra[k], fb = rb[k];
            wA[k] = pack2(fa.x, fa.y);
            wB[k] = pack2(scB * fb.x, scB * fb.y);
        }
        wA[25] = pack2(b_ih[rowA] + b_hh[rowA], W_ih[rowA]);
        wB[25] = pack2(scB * (b_ih[rowB] + b_hh[rowB]), scB * W_ih[rowB]);
    }

    float c0 = 0.0f, c1 = 0.0f;   // cell states (FO lanes), one per batch

    __syncthreads();

#define LSTM_EPI(AS, DS, CC, HW_PTR)                                           \
    {                                                                          \
        float ax, ay, dx, dy;                                                  \
        unpack2(AS, ax, ay); unpack2(DS, dx, dy);                              \
        float sA = sigmoid_f(ax + ay);     /* i (IG) | f (FO) */               \
        float sB = sigmoid_f(dx + dy);     /* (tanh g+1)/2 (IG) | o (FO) */    \
        float val = fmaf(sA + sA, sB, -sA);/* IG: i*g */                       \
        float got = __shfl_xor_sync(0xFFFFFFFFu, val, 16);                     \
        if (role && valid) {                                                   \
            CC = fmaf(sA, CC, got);        /* c = f*c + i*g */                 \
            float s2c = sigmoid_f(CC + CC);                                    \
            (HW_PTR)[p] = fmaf(sB + sB, s2c, -sB);  /* o * tanh(c) */          \
        }                                                                      \
    }

#define LSTM_STEP(HR, HW, T)                                                   \
    {                                                                          \
        u64 as0, ds0, as1, ds1;                                                \
        dot26(wA, wB, &hbuf[0][HR][0], as0, ds0);                              \
        dot26(wA, wB, &hbuf[1][HR][0], as1, ds1);                              \
        LSTM_EPI(as0, ds0, c0, &hbuf[0][HW][0])                                \
        LSTM_EPI(as1, ds1, c1, &hbuf[1][HW][0])                                \
        if (tid == 98) hbuf[0][HW][51] = xs[0][(T) + 1];  /* idle pad thread */\
        if (tid == 99) hbuf[1][HW][51] = xs[1][(T) + 1];                       \
        __syncthreads();                                                       \
    }

    for (int t = 0; t < TN; t += 2) {
        LSTM_STEP(0, 1, t)
        LSTM_STEP(1, 0, t + 1)
    }
#undef LSTM_STEP
#undef LSTM_EPI

    // Final head: out[b] = h_final . W_lin + b_lin  (final h in buf 0)
    if (tid < 2) {
        const float* hf = &hbuf[tid][0][0];
        float s = b_lin[0];
        #pragma unroll
        for (int k = 0; k < HN; k++) s = fmaf(hf[k], W_lin[k], s);
        out[b0 + tid] = s;
    }
}

extern "C" void kernel_launch(void* const* d_in, const int* in_sizes, int n_in,
                              void* d_out, int out_size) {
    const float* x     = (const float*)d_in[0];
    const float* W_ih  = (const float*)d_in[1];
    const float* W_hh  = (const float*)d_in[2];
    const float* b_ih  = (const float*)d_in[3];
    const float* b_hh  = (const float*)d_in[4];
    const float* W_lin = (const float*)d_in[5];
    const float* b_lin = (const float*)d_in[6];
    float* out = (float*)d_out;

    lstm_kernel<<<BN / 2, 128>>>(x, W_ih, W_hh, b_ih, b_hh, W_lin, b_lin, out);
}

// round 12
// speedup vs baseline: 1.3236x; 1.1312x over previous
#include <cuda_runtime.h>

#define HN 50
#define TN 512
#define BN 2048

typedef unsigned long long u64;

__device__ __forceinline__ u64 pack2(float x, float y) {
    u64 r; asm("mov.b64 %0, {%1, %2};" : "=l"(r) : "f"(x), "f"(y)); return r;
}
__device__ __forceinline__ void unpack2(u64 v, float &x, float &y) {
    asm("mov.b64 {%0, %1}, %2;" : "=f"(x), "=f"(y) : "l"(v));
}
// Packed dual-fp32 FMA (Blackwell FFMA2): 2 MACs per issue.
__device__ __forceinline__ u64 fma2(u64 a, u64 b, u64 c) {
    u64 r; asm("fma.rn.f32x2 %0, %1, %2, %3;" : "=l"(r) : "l"(a), "l"(b), "l"(c)); return r;
}
__device__ __forceinline__ u64 add2(u64 a, u64 b) {
    u64 r; asm("add.rn.f32x2 %0, %1, %2;" : "=l"(r) : "l"(a), "l"(b)); return r;
}
// HW tanh (sm_75+): single MUFU op, lat ~16 cyc, max rel err ~2^-11.
__device__ __forceinline__ float tanh_a(float x) {
    float r; asm("tanh.approx.f32 %0, %1;" : "=f"(r) : "f"(x)); return r;
}

__global__ void __launch_bounds__(128, 4)
lstm_kernel(const float* __restrict__ x,     // [B, T, 1]
            const float* __restrict__ W_ih,  // [4H, 1]
            const float* __restrict__ W_hh,  // [4H, H]
            const float* __restrict__ b_ih,  // [4H]
            const float* __restrict__ b_hh,  // [4H]
            const float* __restrict__ W_lin, // [1, H]
            const float* __restrict__ b_lin, // [1]
            float* __restrict__ out)         // [B, 1]
{
    // Double-buffered h row: [0..49]=h, [50]=1 (bias lane), [51]=x_t, pad to 64.
    __shared__ __align__(16) float hbuf[2][64];
    __shared__ float xs[TN + 8];             // padded: step T prefetches xs[T+1]

    const int b    = blockIdx.x;
    const int tid  = threadIdx.x;
    const int lane = tid & 31;
    const int w    = tid >> 5;
    const int p    = (w << 4) | (lane & 15);   // pair h-index, 0..63
    const int role = lane >> 4;                // 0 = IG lane, 1 = FO lane
    const bool valid = (p < HN);
    const int  pc    = valid ? p : (HN - 1);

    // Preload x sequence (coalesced).
    for (int t = tid; t < TN; t += 128) xs[t] = x[b * TN + t];

    // Init h buffers: zeros, 1.0 at slot 50, x_0 at buf0 slot 51.
    if (tid < 128) {
        int idx = tid & 63;
        float v = (idx == 50) ? 1.0f : 0.0f;
        if (idx == 51 && tid < 64) v = x[b * TN];
        ((float*)hbuf)[tid] = v;
    }

    // Gate rows (PyTorch order i,f,g,o): rowA = i|f (sigmoid), rowB = g|o.
    // Sigmoid rows prescaled by 0.5: sigma(z) = 0.5*tanh(z/2) + 0.5.
    // g row (IG lane rowB) unscaled: plain tanh.
    const int rowA = pc + role * HN;           // i (role 0) | f (role 1)
    const int rowB = rowA + 2 * HN;            // g (role 0) | o (role 1)
    const float scA = 0.5f;
    const float scB = role ? 0.5f : 1.0f;

    u64 wA[26], wB[26];
    {
        const float2* ra = (const float2*)(W_hh + rowA * HN);  // 200B row stride
        const float2* rb = (const float2*)(W_hh + rowB * HN);
        #pragma unroll
        for (int k = 0; k < 25; k++) {
            float2 fa = ra[k], fb = rb[k];
            wA[k] = pack2(scA * fa.x, scA * fa.y);
            wB[k] = pack2(scB * fb.x, scB * fb.y);
        }
        wA[25] = pack2(scA * (b_ih[rowA] + b_hh[rowA]), scA * W_ih[rowA]);
        wB[25] = pack2(scB * (b_ih[rowB] + b_hh[rowB]), scB * W_ih[rowB]);
    }

    float c = 0.0f;   // cell state, lives in valid FO lanes

    __syncthreads();

#define LSTM_STEP(HR, HW, T)                                                   \
    {                                                                          \
        const ulonglong2* h2 = (const ulonglong2*)&hbuf[HR][0];                \
        u64 a0 = 0ull, a1 = 0ull, d0 = 0ull, d1 = 0ull;                        \
        _Pragma("unroll")                                                      \
        for (int k = 0; k < 13; k++) {                                         \
            ulonglong2 v = h2[k];            /* LDS.128 broadcast */           \
            a0 = fma2(wA[2 * k],     v.x, a0);                                 \
            a1 = fma2(wA[2 * k + 1], v.y, a1);                                 \
            d0 = fma2(wB[2 * k],     v.x, d0);                                 \
            d1 = fma2(wB[2 * k + 1], v.y, d1);                                 \
        }                                                                      \
        u64 as = add2(a0, a1), ds = add2(d0, d1);                              \
        float ax, ay, dx, dy;                                                  \
        unpack2(as, ax, ay); unpack2(ds, dx, dy);                              \
        float tA = tanh_a(ax + ay);          /* sig arg (i|f), pre-halved */   \
        float tB = tanh_a(dx + dy);          /* g: tanh | o: half-arg */       \
        float iv = fmaf(0.5f, tA, 0.5f);     /* i (IG) | f (FO) */             \
        float prod = iv * tB;                /* IG: i*g  (FO: junk) */         \
        float got = __shfl_xor_sync(0xFFFFFFFFu, prod, 16);                    \
        if (role && valid) {                                                   \
            c = fmaf(iv, c, got);            /* c = f*c + i*g */               \
            float tc = tanh_a(c);                                              \
            float ov = fmaf(0.5f, tB, 0.5f); /* o */                           \
            hbuf[HW][p] = ov * tc;           /* h = o*tanh(c) */               \
        }                                                                      \
        if (tid == 127) hbuf[HW][51] = xs[(T) + 1];  /* idle pad thread */     \
        __syncthreads();                                                       \
    }

    for (int t = 0; t < TN; t += 2) {
        LSTM_STEP(0, 1, t)
        LSTM_STEP(1, 0, t + 1)
    }
#undef LSTM_STEP

    // Final head: out[b] = h_final . W_lin + b_lin  (final h in buf 0)
    if (tid == 0) {
        float s = b_lin[0];
        #pragma unroll
        for (int k = 0; k < HN; k++) s = fmaf(hbuf[0][k], W_lin[k], s);
        out[b] = s;
    }
}

extern "C" void kernel_launch(void* const* d_in, const int* in_sizes, int n_in,
                              void* d_out, int out_size) {
    const float* x     = (const float*)d_in[0];
    const float* W_ih  = (const float*)d_in[1];
    const float* W_hh  = (const float*)d_in[2];
    const float* b_ih  = (const float*)d_in[3];
    const float* b_hh  = (const float*)d_in[4];
    const float* W_lin = (const float*)d_in[5];
    const float* b_lin = (const float*)d_in[6];
    float* out = (float*)d_out;

    lstm_kernel<<<BN, 128>>>(x, W_ih, W_hh, b_ih, b_hh, W_lin, b_lin, out);
}